// round 13
// baseline (speedup 1.0000x reference)
#include <cuda_runtime.h>
#include <cuda_bf16.h>
#include <math.h>
#include <stdint.h>

// ---------------------------------------------------------------------------
// Problem constants
// ---------------------------------------------------------------------------
#define TT   2048      // seq len T
#define HIDD 2048      // hidden dim
#define NH   16        // q heads
#define NKV  8         // kv heads
#define HD   128       // head dim
#define II   8192      // mlp intermediate
#define EPSF 1e-6f
#define SCALEF 0.08838834764831845f   // 1/sqrt(128)

// ---------------------------------------------------------------------------
// Scratch (device globals; no allocation allowed)
// ---------------------------------------------------------------------------
__device__ float g_x      [TT * HIDD];        // raw input, transposed to [T][HID]
__device__ float g_q      [TT * NH  * HD];    // fp32 q (pre-rope)
__device__ float g_k      [TT * NKV * HD];    // fp32 k (pre-rope)
__device__ float g_hidden [TT * HIDD];        // residual after attention
__device__ float g_final  [TT * HIDD];        // final hidden (pre-transpose)
__device__ float g_rms    [TT];               // input-ln inv-rms per t

// bf16 hi/lo split operands
__device__ __nv_bfloat16 g_h_hi  [TT * HIDD],      g_h_lo  [TT * HIDD];
__device__ __nv_bfloat16 g_h2_hi [TT * HIDD],      g_h2_lo [TT * HIDD];
__device__ __nv_bfloat16 g_ao_hi [TT * NH * HD],   g_ao_lo [TT * NH * HD];
__device__ __nv_bfloat16 g_act_hi[TT * II],        g_act_lo[TT * II];
__device__ __nv_bfloat16 g_qh[TT * NH * HD],       g_ql[TT * NH * HD];     // post-rope q * SCALE
__device__ __nv_bfloat16 g_kh[TT * NKV * HD],      g_kl[TT * NKV * HD];    // post-rope k
__device__ __nv_bfloat16 g_vh[TT * NKV * HD],      g_vl[TT * NKV * HD];    // v
__device__ __nv_bfloat16 g_wqkv_hi[(NH + 2 * NKV) * HD * HIDD], g_wqkv_lo[(NH + 2 * NKV) * HD * HIDD];
__device__ __nv_bfloat16 g_wo_hi [HIDD * NH * HD], g_wo_lo [HIDD * NH * HD];
__device__ __nv_bfloat16 g_wgu_hi[2 * II * HIDD],  g_wgu_lo[2 * II * HIDD];  // gate/up row-interleaved
__device__ __nv_bfloat16 g_wd_hi [HIDD * II],      g_wd_lo [HIDD * II];

// ---------------------------------------------------------------------------
// base-ISA PTX helpers (compute_103-safe: cp.async / ldmatrix / mma.sync)
// ---------------------------------------------------------------------------
__device__ __forceinline__ uint32_t smem_u32(const void* p) {
    uint32_t a;
    asm("{ .reg .u64 t; cvta.to.shared.u64 t, %1; cvt.u32.u64 %0, t; }"
        : "=r"(a) : "l"(p));
    return a;
}
#define CPA(dst, src) \
    asm volatile("cp.async.cg.shared.global [%0], [%1], 16;" :: "r"(dst), "l"(src))
#define CPA_COMMIT() asm volatile("cp.async.commit_group;" ::: "memory")
#define CPA_WAIT(n)  asm volatile("cp.async.wait_group %0;" :: "n"(n) : "memory")

#define LDSM4(r0, r1, r2, r3, a) \
    asm volatile("ldmatrix.sync.aligned.m8n8.x4.shared.b16 {%0,%1,%2,%3}, [%4];" \
                 : "=r"(r0), "=r"(r1), "=r"(r2), "=r"(r3) : "r"(a))
#define LDSM4T(r0, r1, r2, r3, a) \
    asm volatile("ldmatrix.sync.aligned.m8n8.x4.trans.shared.b16 {%0,%1,%2,%3}, [%4];" \
                 : "=r"(r0), "=r"(r1), "=r"(r2), "=r"(r3) : "r"(a))

#define MMA16816(c, a0, a1, a2, a3, b0, b1) \
    asm volatile("mma.sync.aligned.m16n8k16.row.col.f32.bf16.bf16.f32 " \
                 "{%0,%1,%2,%3}, {%4,%5,%6,%7}, {%8,%9}, {%0,%1,%2,%3};" \
                 : "+f"((c)[0]), "+f"((c)[1]), "+f"((c)[2]), "+f"((c)[3]) \
                 : "r"(a0), "r"(a1), "r"(a2), "r"(a3), "r"(b0), "r"(b1))

__device__ __forceinline__ uint32_t pack_hi2(float a, float b, float& ra, float& rb) {
    __nv_bfloat16 ha = __float2bfloat16(a), hb = __float2bfloat16(b);
    ra = a - __bfloat162float(ha);
    rb = b - __bfloat162float(hb);
    __nv_bfloat162 t; t.x = ha; t.y = hb;
    return *(uint32_t*)&t;
}
__device__ __forceinline__ uint32_t pack2(float a, float b) {
    __nv_bfloat162 t; t.x = __float2bfloat16(a); t.y = __float2bfloat16(b);
    return *(uint32_t*)&t;
}

// ---------------------------------------------------------------------------
// 1) input RMS pass 1
// ---------------------------------------------------------------------------
__global__ void k_rms_in_pass1(const float* __restrict__ hc) {
    int tx = threadIdx.x, ty = threadIdx.y;         // 32 x 8
    int t = blockIdx.x * 32 + tx;
    float ss = 0.f;
    for (int c = ty; c < HIDD; c += 8) {
        float v = hc[c * TT + t];
        ss += v * v;
    }
    __shared__ float red[8][32];
    red[ty][tx] = ss;
    __syncthreads();
    if (ty == 0) {
        float s = 0.f;
        #pragma unroll
        for (int i = 0; i < 8; i++) s += red[i][tx];
        g_rms[t] = rsqrtf(s * (1.0f / HIDD) + EPSF);
    }
}

// ---------------------------------------------------------------------------
// 2) transpose + scale
// ---------------------------------------------------------------------------
__global__ void k_norm_transpose(const float* __restrict__ hc,
                                 const float* __restrict__ w) {
    __shared__ float tile[32][33];
    int t0 = blockIdx.x * 32, c0 = blockIdx.y * 32;
    int tx = threadIdx.x, ty = threadIdx.y;          // 32 x 8
    for (int i = ty; i < 32; i += 8)
        tile[i][tx] = hc[(c0 + i) * TT + t0 + tx];
    __syncthreads();
    for (int i = ty; i < 32; i += 8) {
        int t = t0 + i, c = c0 + tx;
        float val = tile[tx][i];
        g_x[(size_t)t * HIDD + c] = val;
        float nv = val * g_rms[t] * w[c];
        __nv_bfloat16 hv = __float2bfloat16(nv);
        g_h_hi[(size_t)t * HIDD + c] = hv;
        g_h_lo[(size_t)t * HIDD + c] = __float2bfloat16(nv - __bfloat162float(hv));
    }
}

// ---------------------------------------------------------------------------
// 3) weight fp32 -> bf16 hi/lo conversion (8 elems/thread, vector I/O)
// ---------------------------------------------------------------------------
__global__ void k_wconv(const float* __restrict__ src,
                        __nv_bfloat16* __restrict__ hi,
                        __nv_bfloat16* __restrict__ lo, int n) {
    int i8 = (blockIdx.x * 256 + threadIdx.x) * 8;
    if (i8 >= n) return;
    float4 v0 = *(const float4*)(src + i8);
    float4 v1 = *(const float4*)(src + i8 + 4);
    float vv[8] = {v0.x, v0.y, v0.z, v0.w, v1.x, v1.y, v1.z, v1.w};
    __nv_bfloat16 hb[8], lb[8];
    #pragma unroll
    for (int j = 0; j < 8; j++) {
        hb[j] = __float2bfloat16(vv[j]);
        lb[j] = __float2bfloat16(vv[j] - __bfloat162float(hb[j]));
    }
    *(uint4*)(hi + i8) = *(uint4*)hb;
    *(uint4*)(lo + i8) = *(uint4*)lb;
}

// gate_up weights: interleave gate row i -> 2i, up row i -> 2i+1
__global__ void k_wconv_ilv(const float* __restrict__ src) {
    int i8 = (blockIdx.x * 256 + threadIdx.x) * 8;
    int row = i8 / HIDD;
    int col = i8 % HIDD;
    int drow = (row < II) ? 2 * row : 2 * (row - II) + 1;
    size_t dofs = (size_t)drow * HIDD + col;
    float4 v0 = *(const float4*)(src + i8);
    float4 v1 = *(const float4*)(src + i8 + 4);
    float vv[8] = {v0.x, v0.y, v0.z, v0.w, v1.x, v1.y, v1.z, v1.w};
    __nv_bfloat16 hb[8], lb[8];
    #pragma unroll
    for (int j = 0; j < 8; j++) {
        hb[j] = __float2bfloat16(vv[j]);
        lb[j] = __float2bfloat16(vv[j] - __bfloat162float(hb[j]));
    }
    *(uint4*)(g_wgu_hi + dofs) = *(uint4*)hb;
    *(uint4*)(g_wgu_lo + dofs) = *(uint4*)lb;
}

// ---------------------------------------------------------------------------
// 4) mma.sync bf16 GEMM (3-term hi/lo). 128x128x32 CTA, 8 warps (2m x 4n).
//    MODE 0: fp32 store   MODE 1: fp32 store + aux residual
//    MODE 2: QKV routing (q,k fp32; v bf16 hi/lo)
//    MODE 3: fused SwiGLU -> act bf16 hi/lo (gate/up interleaved cols)
// ---------------------------------------------------------------------------
#define TILE_BYTES (128 * 40 * 2)      // 10240
#define OFF_AH 0
#define OFF_AL (1 * TILE_BYTES)
#define OFF_BH (2 * TILE_BYTES)
#define OFF_BL (3 * TILE_BYTES)
#define STG_BYTES (4 * TILE_BYTES)     // 40960
#define MM_SMEM (2 * STG_BYTES)        // 81920

__device__ __forceinline__ void bmma_load_stage(
    uint32_t sbase, const __nv_bfloat16* Ah, const __nv_bfloat16* Al,
    const __nv_bfloat16* Bh, const __nv_bfloat16* Bl,
    int m0, int n0, int K, int kc, int tid)
{
    int r = tid >> 2, seg = tid & 3;
    size_t kof = (size_t)kc * 32 + seg * 8;
    uint32_t dst = sbase + r * 80 + seg * 16;
    const __nv_bfloat16* pa = Ah + (size_t)(m0 + r) * K + kof;
    const __nv_bfloat16* pl = Al + (size_t)(m0 + r) * K + kof;
    const __nv_bfloat16* pb = Bh + (size_t)(n0 + r) * K + kof;
    const __nv_bfloat16* pq = Bl + (size_t)(n0 + r) * K + kof;
    size_t half = (size_t)64 * K;
    CPA(dst + OFF_AH, pa);  CPA(dst + OFF_AH + 64 * 80, pa + half);
    CPA(dst + OFF_AL, pl);  CPA(dst + OFF_AL + 64 * 80, pl + half);
    CPA(dst + OFF_BH, pb);  CPA(dst + OFF_BH + 64 * 80, pb + half);
    CPA(dst + OFF_BL, pq);  CPA(dst + OFF_BL + 64 * 80, pq + half);
}

template <int MODE>
__global__ __launch_bounds__(256)
void k_bmma(const __nv_bfloat16* __restrict__ Ah, const __nv_bfloat16* __restrict__ Al,
            const __nv_bfloat16* __restrict__ Bh, const __nv_bfloat16* __restrict__ Bl,
            float* __restrict__ Cbase, const float* __restrict__ aux,
            int K, int N) {
    extern __shared__ char smem[];
    uint32_t sb = smem_u32(smem);
    int tid = threadIdx.x;
    int m0 = blockIdx.y * 128, n0 = blockIdx.x * 128;
    int warp = tid >> 5, lane = tid & 31;
    int wm = warp >> 2, wn = warp & 3;

    float acc[4][4][4];
    #pragma unroll
    for (int i = 0; i < 4; i++)
        #pragma unroll
        for (int j = 0; j < 4; j++)
            #pragma unroll
            for (int v = 0; v < 4; v++) acc[i][j][v] = 0.f;

    uint32_t a_off = (lane & 15) * 80 + (lane >> 4) * 16;
    uint32_t b_off = ((lane >> 4) * 8 + (lane & 7)) * 80 + ((lane >> 3) & 1) * 16;

    const int KC = K / 32;

    bmma_load_stage(sb, Ah, Al, Bh, Bl, m0, n0, K, 0, tid);
    CPA_COMMIT();

    for (int kc = 0; kc < KC; kc++) {
        int s = kc & 1;
        if (kc + 1 < KC) {
            bmma_load_stage(sb + (s ^ 1) * STG_BYTES, Ah, Al, Bh, Bl, m0, n0, K, kc + 1, tid);
            CPA_COMMIT();
            CPA_WAIT(1);
        } else {
            CPA_WAIT(0);
        }
        __syncthreads();

        uint32_t stg = sb + s * STG_BYTES;
        uint32_t aBase = stg + wm * (64 * 80) + a_off;
        uint32_t bBase = stg + wn * (32 * 80) + b_off;

        #pragma unroll
        for (int ks = 0; ks < 2; ks++) {
            uint32_t ko = ks * 32;
            uint32_t ah[4][4], al[4][4], bh[4][2], bl[4][2];
            #pragma unroll
            for (int im = 0; im < 4; im++)
                LDSM4(ah[im][0], ah[im][1], ah[im][2], ah[im][3],
                      aBase + OFF_AH + im * (16 * 80) + ko);
            #pragma unroll
            for (int g = 0; g < 2; g++) {
                uint32_t r0, r1, r2, r3;
                LDSM4(r0, r1, r2, r3, bBase + OFF_BH + g * (16 * 80) + ko);
                bh[g * 2 + 0][0] = r0; bh[g * 2 + 0][1] = r1;
                bh[g * 2 + 1][0] = r2; bh[g * 2 + 1][1] = r3;
            }
            #pragma unroll
            for (int im = 0; im < 4; im++)
                #pragma unroll
                for (int in = 0; in < 4; in++)
                    MMA16816(acc[im][in], ah[im][0], ah[im][1], ah[im][2], ah[im][3],
                             bh[in][0], bh[in][1]);
            #pragma unroll
            for (int g = 0; g < 2; g++) {
                uint32_t r0, r1, r2, r3;
                LDSM4(r0, r1, r2, r3, bBase + OFF_BL + g * (16 * 80) + ko);
                bl[g * 2 + 0][0] = r0; bl[g * 2 + 0][1] = r1;
                bl[g * 2 + 1][0] = r2; bl[g * 2 + 1][1] = r3;
            }
            #pragma unroll
            for (int im = 0; im < 4; im++)
                #pragma unroll
                for (int in = 0; in < 4; in++)
                    MMA16816(acc[im][in], ah[im][0], ah[im][1], ah[im][2], ah[im][3],
                             bl[in][0], bl[in][1]);
            #pragma unroll
            for (int im = 0; im < 4; im++)
                LDSM4(al[im][0], al[im][1], al[im][2], al[im][3],
                      aBase + OFF_AL + im * (16 * 80) + ko);
            #pragma unroll
            for (int im = 0; im < 4; im++)
                #pragma unroll
                for (int in = 0; in < 4; in++)
                    MMA16816(acc[im][in], al[im][0], al[im][1], al[im][2], al[im][3],
                             bh[in][0], bh[in][1]);
        }
        __syncthreads();
    }

    // ---- epilogue: regs -> smem (pitch 132) ----
    float* stile = (float*)smem;
    int qrow = lane >> 2, qcol = (lane & 3) * 2;
    #pragma unroll
    for (int im = 0; im < 4; im++) {
        int r0 = wm * 64 + im * 16 + qrow;
        #pragma unroll
        for (int in = 0; in < 4; in++) {
            int c = wn * 32 + in * 8 + qcol;
            stile[(size_t)r0 * 132 + c]           = acc[im][in][0];
            stile[(size_t)r0 * 132 + c + 1]       = acc[im][in][1];
            stile[(size_t)(r0 + 8) * 132 + c]     = acc[im][in][2];
            stile[(size_t)(r0 + 8) * 132 + c + 1] = acc[im][in][3];
        }
    }
    __syncthreads();

    if (MODE == 3) {
        // fused SwiGLU: cols alternate gate/up, act col = n0/2 + j
        #pragma unroll
        for (int it = 0; it < 32; it++) {
            int idx = it * 256 + tid;
            int m = idx >> 6, j = idx & 63;
            float g = stile[(size_t)m * 132 + 2 * j];
            float u = stile[(size_t)m * 132 + 2 * j + 1];
            float a = (g / (1.0f + __expf(-g))) * u;
            __nv_bfloat16 hv = __float2bfloat16(a);
            size_t go = (size_t)(m0 + m) * II + (n0 >> 1) + j;
            g_act_hi[go] = hv;
            g_act_lo[go] = __float2bfloat16(a - __bfloat162float(hv));
        }
        return;
    }

    if (MODE == 2 && n0 >= (NH + NKV) * HD) {
        // v range: bf16 hi/lo
        int ncol = n0 - (NH + NKV) * HD;
        #pragma unroll
        for (int st = 0; st < 16; st++) {
            int idx = st * 256 + tid;
            int m = idx >> 5;
            int c4 = (idx & 31) * 4;
            const float* srow = &stile[(size_t)m * 132 + c4];
            __nv_bfloat16 hb[4], lb[4];
            #pragma unroll
            for (int j = 0; j < 4; j++) {
                float v = srow[j];
                hb[j] = __float2bfloat16(v);
                lb[j] = __float2bfloat16(v - __bfloat162float(hb[j]));
            }
            size_t go = (size_t)(m0 + m) * (NKV * HD) + ncol + c4;
            *(uint2*)&g_vh[go] = *(uint2*)hb;
            *(uint2*)&g_vl[go] = *(uint2*)lb;
        }
        return;
    }

    float* Cp; int ldc; int ncol;
    if (MODE == 2) {
        if (n0 < NH * HD) { Cp = g_q; ldc = NH * HD;  ncol = n0; }
        else              { Cp = g_k; ldc = NKV * HD; ncol = n0 - NH * HD; }
    } else { Cp = Cbase; ldc = N; ncol = n0; }

    #pragma unroll
    for (int st = 0; st < 16; st++) {
        int idx = st * 256 + tid;
        int m = idx >> 5;
        int c4 = (idx & 31) * 4;
        const float* srow = &stile[(size_t)m * 132 + c4];
        float4 v;
        v.x = srow[0]; v.y = srow[1]; v.z = srow[2]; v.w = srow[3];
        size_t go = (size_t)(m0 + m) * ldc + ncol + c4;
        if (MODE == 1) {
            float4 a4 = *(const float4*)(aux + go);
            v.x += a4.x; v.y += a4.y; v.z += a4.z; v.w += a4.w;
        }
        *(float4*)(Cp + go) = v;
    }
}

// ---------------------------------------------------------------------------
// 5) per-(t,head) RMSNorm + RoPE -> bf16 hi/lo (q scaled by 1/sqrt(d))
// ---------------------------------------------------------------------------
__global__ void k_qknorm_rope(const float* __restrict__ cosb,
                              const float* __restrict__ sinb,
                              const float* __restrict__ qw,
                              const float* __restrict__ kw) {
    int t = blockIdx.x;
    int head = blockIdx.y;
    const float* buf; const float* w; size_t off; bool isq;
    if (head < NH) { buf = g_q; off = (size_t)(t * NH + head) * HD; w = qw; isq = true; }
    else           { buf = g_k; off = (size_t)(t * NKV + (head - NH)) * HD; w = kw; isq = false; }
    int d = threadIdx.x;
    float v = buf[off + d];
    float ss = v * v;
    #pragma unroll
    for (int o = 16; o; o >>= 1) ss += __shfl_xor_sync(~0u, ss, o);
    __shared__ float ws[4];
    if ((d & 31) == 0) ws[d >> 5] = ss;
    __syncthreads();
    float tot = ws[0] + ws[1] + ws[2] + ws[3];
    float r = rsqrtf(tot * (1.0f / HD) + EPSF);
    __shared__ float sh[HD];
    sh[d] = v * r * w[d];
    __syncthreads();
    float rot = (d < 64) ? -sh[d + 64] : sh[d - 64];
    float val = sh[d] * cosb[t * HD + d] + rot * sinb[t * HD + d];
    if (isq) {
        val *= SCALEF;
        __nv_bfloat16 hv = __float2bfloat16(val);
        g_qh[off + d] = hv;
        g_ql[off + d] = __float2bfloat16(val - __bfloat162float(hv));
    } else {
        __nv_bfloat16 hv = __float2bfloat16(val);
        g_kh[off + d] = hv;
        g_kl[off + d] = __float2bfloat16(val - __bfloat162float(hv));
    }
}

// ---------------------------------------------------------------------------
// 6) mma.sync flash attention, causal.
//    CTA: 128 q-rows x 1 head, 8 warps (16 rows each), KV tiles of 64,
//    double-buffered cp.async. 3-term hi/lo on both GEMMs.
//    smem pitch 272 B (128 bf16 + 8 pad) -> conflict-free ldmatrix.
// ---------------------------------------------------------------------------
#define AP 272
#define AQB (128 * AP)            // one Q array (hi or lo)
#define ATB (64 * AP)             // one KV tile array
#define ASTG (4 * ATB)            // Kh,Kl,Vh,Vl
#define A_SMEM (2 * AQB + 2 * ASTG)   // 208896

__device__ __forceinline__ void attn_load_kv(uint32_t stg, int kt, int kvh, int tid) {
    #pragma unroll
    for (int i = 0; i < 4; i++) {
        int idx = i * 256 + tid;
        int r = idx >> 4, c = idx & 15;
        size_t so = (size_t)(kt * 64 + r) * (NKV * HD) + kvh * HD + c * 8;
        uint32_t d = stg + r * AP + c * 16;
        CPA(d,           g_kh + so);
        CPA(d + ATB,     g_kl + so);
        CPA(d + 2 * ATB, g_vh + so);
        CPA(d + 3 * ATB, g_vl + so);
    }
}

__global__ __launch_bounds__(256)
void k_attn() {
    extern __shared__ char smem[];
    uint32_t sb = smem_u32(smem);
    int tid = threadIdx.x, lane = tid & 31, warp = tid >> 5;
    int qt = 15 - (int)blockIdx.x;          // big tiles first
    int h = blockIdx.y, kvh = h >> 1;

    uint32_t sQh = sb, sQl = sb + AQB;
    uint32_t sStg = sb + 2 * AQB;

    // Q tile load (rows qt*128..+127, cols h*128..+127), hi+lo
    #pragma unroll
    for (int i = 0; i < 8; i++) {
        int idx = i * 256 + tid;
        int r = idx >> 4, c = idx & 15;
        size_t so = (size_t)(qt * 128 + r) * (NH * HD) + h * HD + c * 8;
        CPA(sQh + r * AP + c * 16, g_qh + so);
        CPA(sQl + r * AP + c * 16, g_ql + so);
    }
    CPA_COMMIT();
    attn_load_kv(sStg, 0, kvh, tid);
    CPA_COMMIT();

    uint32_t a_off = (lane & 15) * AP + (lane >> 4) * 16;                       // A frag / V-trans
    uint32_t b_off = ((lane >> 4) * 8 + (lane & 7)) * AP + ((lane >> 3) & 1) * 16;  // B frag (K)

    float o[16][4];
    #pragma unroll
    for (int i = 0; i < 16; i++)
        #pragma unroll
        for (int j = 0; j < 4; j++) o[i][j] = 0.f;
    float m0 = -1e30f, m1 = -1e30f, l0 = 0.f, l1 = 0.f;

    int row0 = qt * 128 + warp * 16 + (lane >> 2);    // thread's first q row
    const int ktlast = 2 * qt + 1;

    for (int kt = 0; kt <= ktlast; kt++) {
        uint32_t stg = sStg + (kt & 1) * ASTG;
        if (kt < ktlast) {
            attn_load_kv(sStg + ((kt + 1) & 1) * ASTG, kt + 1, kvh, tid);
            CPA_COMMIT();
            CPA_WAIT(1);
        } else {
            CPA_WAIT(0);
        }
        __syncthreads();

        // ---- S = Q K^T (3-term), 16q x 64s per warp ----
        float sacc[8][4];
        #pragma unroll
        for (int i = 0; i < 8; i++)
            #pragma unroll
            for (int j = 0; j < 4; j++) sacc[i][j] = 0.f;

        uint32_t aQhW = sQh + warp * (16 * AP) + a_off;
        uint32_t aQlW = sQl + warp * (16 * AP) + a_off;

        #pragma unroll
        for (int ks = 0; ks < 8; ks++) {
            uint32_t ko = ks * 32;
            uint32_t ah0, ah1, ah2, ah3, al0, al1, al2, al3;
            LDSM4(ah0, ah1, ah2, ah3, aQhW + ko);
            LDSM4(al0, al1, al2, al3, aQlW + ko);
            #pragma unroll
            for (int half = 0; half < 2; half++) {
                uint32_t kb = stg + half * (32 * AP) + ko + b_off;
                uint32_t bh[4][2], bl[4][2];
                {
                    uint32_t r0, r1, r2, r3;
                    LDSM4(r0, r1, r2, r3, kb);
                    bh[0][0] = r0; bh[0][1] = r1; bh[1][0] = r2; bh[1][1] = r3;
                    LDSM4(r0, r1, r2, r3, kb + 16 * AP);
                    bh[2][0] = r0; bh[2][1] = r1; bh[3][0] = r2; bh[3][1] = r3;
                }
                #pragma unroll
                for (int in = 0; in < 4; in++)
                    MMA16816(sacc[half * 4 + in], ah0, ah1, ah2, ah3, bh[in][0], bh[in][1]);
                #pragma unroll
                for (int in = 0; in < 4; in++)
                    MMA16816(sacc[half * 4 + in], al0, al1, al2, al3, bh[in][0], bh[in][1]);
                {
                    uint32_t r0, r1, r2, r3;
                    LDSM4(r0, r1, r2, r3, kb + ATB);
                    bl[0][0] = r0; bl[0][1] = r1; bl[1][0] = r2; bl[1][1] = r3;
                    LDSM4(r0, r1, r2, r3, kb + ATB + 16 * AP);
                    bl[2][0] = r0; bl[2][1] = r1; bl[3][0] = r2; bl[3][1] = r3;
                }
                #pragma unroll
                for (int in = 0; in < 4; in++)
                    MMA16816(sacc[half * 4 + in], ah0, ah1, ah2, ah3, bl[in][0], bl[in][1]);
            }
        }

        // ---- causal mask (only near diagonal) ----
        if (kt >= 2 * qt) {
            #pragma unroll
            for (int nt = 0; nt < 8; nt++) {
                int colb = kt * 64 + nt * 8 + (lane & 3) * 2;
                if (colb > row0)      sacc[nt][0] = -1e30f;
                if (colb + 1 > row0)  sacc[nt][1] = -1e30f;
                if (colb > row0 + 8)  sacc[nt][2] = -1e30f;
                if (colb + 1 > row0 + 8) sacc[nt][3] = -1e30f;
            }
        }

        // ---- online softmax (rows row0, row0+8) ----
        float mx0 = m0, mx1 = m1;
        #pragma unroll
        for (int nt = 0; nt < 8; nt++) {
            mx0 = fmaxf(mx0, fmaxf(sacc[nt][0], sacc[nt][1]));
            mx1 = fmaxf(mx1, fmaxf(sacc[nt][2], sacc[nt][3]));
        }
        mx0 = fmaxf(mx0, __shfl_xor_sync(~0u, mx0, 1));
        mx0 = fmaxf(mx0, __shfl_xor_sync(~0u, mx0, 2));
        mx1 = fmaxf(mx1, __shfl_xor_sync(~0u, mx1, 1));
        mx1 = fmaxf(mx1, __shfl_xor_sync(~0u, mx1, 2));
        float alp0 = __expf(m0 - mx0), alp1 = __expf(m1 - mx1);
        float ls0 = 0.f, ls1 = 0.f;
        #pragma unroll
        for (int nt = 0; nt < 8; nt++) {
            sacc[nt][0] = __expf(sacc[nt][0] - mx0);
            sacc[nt][1] = __expf(sacc[nt][1] - mx0);
            sacc[nt][2] = __expf(sacc[nt][2] - mx1);
            sacc[nt][3] = __expf(sacc[nt][3] - mx1);
            ls0 += sacc[nt][0] + sacc[nt][1];
            ls1 += sacc[nt][2] + sacc[nt][3];
        }
        ls0 += __shfl_xor_sync(~0u, ls0, 1);
        ls0 += __shfl_xor_sync(~0u, ls0, 2);
        ls1 += __shfl_xor_sync(~0u, ls1, 1);
        ls1 += __shfl_xor_sync(~0u, ls1, 2);
        l0 = l0 * alp0 + ls0;  m0 = mx0;
        l1 = l1 * alp1 + ls1;  m1 = mx1;
        #pragma unroll
        for (int nt = 0; nt < 16; nt++) {
            o[nt][0] *= alp0; o[nt][1] *= alp0;
            o[nt][2] *= alp1; o[nt][3] *= alp1;
        }

        // ---- O += P V (3-term); V via ldmatrix.trans ----
        #pragma unroll
        for (int ks = 0; ks < 4; ks++) {
            float r0f, r1f, r2f, r3f, r4f, r5f, r6f, r7f;
            uint32_t ah0 = pack_hi2(sacc[2 * ks][0],     sacc[2 * ks][1],     r0f, r1f);
            uint32_t ah1 = pack_hi2(sacc[2 * ks][2],     sacc[2 * ks][3],     r2f, r3f);
            uint32_t ah2 = pack_hi2(sacc[2 * ks + 1][0], sacc[2 * ks + 1][1], r4f, r5f);
            uint32_t ah3 = pack_hi2(sacc[2 * ks + 1][2], sacc[2 * ks + 1][3], r6f, r7f);
            uint32_t pl0 = pack2(r0f, r1f), pl1 = pack2(r2f, r3f);
            uint32_t pl2 = pack2(r4f, r5f), pl3 = pack2(r6f, r7f);
            uint32_t vbase = stg + 2 * ATB + ks * (16 * AP) + a_off;
            #pragma unroll
            for (int vt = 0; vt < 8; vt++) {
                uint32_t v0, v1, v2, v3;
                LDSM4T(v0, v1, v2, v3, vbase + vt * 32);
                MMA16816(o[2 * vt],     ah0, ah1, ah2, ah3, v0, v1);
                MMA16816(o[2 * vt + 1], ah0, ah1, ah2, ah3, v2, v3);
                MMA16816(o[2 * vt],     pl0, pl1, pl2, pl3, v0, v1);
                MMA16816(o[2 * vt + 1], pl0, pl1, pl2, pl3, v2, v3);
                LDSM4T(v0, v1, v2, v3, vbase + ATB + vt * 32);
                MMA16816(o[2 * vt],     ah0, ah1, ah2, ah3, v0, v1);
                MMA16816(o[2 * vt + 1], ah0, ah1, ah2, ah3, v2, v3);
            }
        }
        __syncthreads();
    }

    // ---- normalize + store bf16 hi/lo ----
    float i0 = 1.0f / l0, i1 = 1.0f / l1;
    int colb = h * HD + (lane & 3) * 2;
    #pragma unroll
    for (int nt = 0; nt < 16; nt++) {
        float ra, rb;
        uint32_t hi0 = pack_hi2(o[nt][0] * i0, o[nt][1] * i0, ra, rb);
        uint32_t lo0 = pack2(ra, rb);
        size_t go = (size_t)row0 * (NH * HD) + colb + nt * 8;
        *(uint32_t*)&g_ao_hi[go] = hi0;
        *(uint32_t*)&g_ao_lo[go] = lo0;
        uint32_t hi1 = pack_hi2(o[nt][2] * i1, o[nt][3] * i1, ra, rb);
        uint32_t lo1 = pack2(ra, rb);
        size_t g1 = (size_t)(row0 + 8) * (NH * HD) + colb + nt * 8;
        *(uint32_t*)&g_ao_hi[g1] = hi1;
        *(uint32_t*)&g_ao_lo[g1] = lo1;
    }
}

// ---------------------------------------------------------------------------
// 7) post-attention RMSNorm -> h2 bf16 hi/lo
// ---------------------------------------------------------------------------
__global__ void k_rms_post(const float* __restrict__ w) {
    int t = blockIdx.x;
    int tid = threadIdx.x;                   // 256
    const float* row = g_hidden + (size_t)t * HIDD;
    float ss = 0.f;
    for (int c = tid; c < HIDD; c += 256) { float v = row[c]; ss += v * v; }
    #pragma unroll
    for (int o = 16; o; o >>= 1) ss += __shfl_xor_sync(~0u, ss, o);
    __shared__ float wsum[8];
    if ((tid & 31) == 0) wsum[tid >> 5] = ss;
    __syncthreads();
    if (tid < 32) {
        float s = (tid < 8) ? wsum[tid] : 0.f;
        #pragma unroll
        for (int o = 4; o; o >>= 1) s += __shfl_xor_sync(~0u, s, o);
        if (tid == 0) wsum[0] = rsqrtf(s * (1.0f / HIDD) + EPSF);
    }
    __syncthreads();
    float r = wsum[0];
    for (int c = tid; c < HIDD; c += 256) {
        float nv = row[c] * r * w[c];
        __nv_bfloat16 hv = __float2bfloat16(nv);
        g_h2_hi[(size_t)t * HIDD + c] = hv;
        g_h2_lo[(size_t)t * HIDD + c] = __float2bfloat16(nv - __bfloat162float(hv));
    }
}

// ---------------------------------------------------------------------------
// 8) final transpose: out[c*T + t] = g_final[t*HID + c]
// ---------------------------------------------------------------------------
__global__ void k_transpose_out(float* __restrict__ out) {
    __shared__ float tile[32][33];
    int t0 = blockIdx.x * 32, c0 = blockIdx.y * 32;
    int tx = threadIdx.x, ty = threadIdx.y;     // 32 x 8
    for (int i = ty; i < 32; i += 8)
        tile[i][tx] = g_final[(size_t)(t0 + i) * HIDD + c0 + tx];
    __syncthreads();
    for (int i = ty; i < 32; i += 8)
        out[(size_t)(c0 + i) * TT + t0 + tx] = tile[tx][i];
}

// ---------------------------------------------------------------------------
// launch
// ---------------------------------------------------------------------------
extern "C" void kernel_launch(void* const* d_in, const int* in_sizes, int n_in,
                              void* d_out, int out_size) {
    const float* hc   = (const float*)d_in[0];
    const float* cosb = (const float*)d_in[1];
    const float* sinb = (const float*)d_in[2];
    // d_in[3] causal_mask, d_in[4] kv_cache, d_in[15] current_pos: unused
    const float* wq  = (const float*)d_in[5];
    const float* wk  = (const float*)d_in[6];
    const float* wv  = (const float*)d_in[7];
    const float* wo  = (const float*)d_in[8];
    const float* wgu = (const float*)d_in[9];
    const float* wd  = (const float*)d_in[10];
    const float* ilw = (const float*)d_in[11];
    const float* plw = (const float*)d_in[12];
    const float* qnw = (const float*)d_in[13];
    const float* knw = (const float*)d_in[14];
    float* out = (float*)d_out;

    float *p_x, *p_hid, *p_fin;
    cudaGetSymbolAddress((void**)&p_x,   g_x);
    cudaGetSymbolAddress((void**)&p_hid, g_hidden);
    cudaGetSymbolAddress((void**)&p_fin, g_final);

    __nv_bfloat16 *b_h_hi, *b_h_lo, *b_h2_hi, *b_h2_lo, *b_ao_hi, *b_ao_lo,
                  *b_act_hi, *b_act_lo, *b_wqkv_hi, *b_wqkv_lo, *b_wo_hi, *b_wo_lo,
                  *b_wgu_hi, *b_wgu_lo, *b_wd_hi, *b_wd_lo;
    cudaGetSymbolAddress((void**)&b_h_hi,   g_h_hi);
    cudaGetSymbolAddress((void**)&b_h_lo,   g_h_lo);
    cudaGetSymbolAddress((void**)&b_h2_hi,  g_h2_hi);
    cudaGetSymbolAddress((void**)&b_h2_lo,  g_h2_lo);
    cudaGetSymbolAddress((void**)&b_ao_hi,  g_ao_hi);
    cudaGetSymbolAddress((void**)&b_ao_lo,  g_ao_lo);
    cudaGetSymbolAddress((void**)&b_act_hi, g_act_hi);
    cudaGetSymbolAddress((void**)&b_act_lo, g_act_lo);
    cudaGetSymbolAddress((void**)&b_wqkv_hi, g_wqkv_hi);
    cudaGetSymbolAddress((void**)&b_wqkv_lo, g_wqkv_lo);
    cudaGetSymbolAddress((void**)&b_wo_hi,  g_wo_hi);
    cudaGetSymbolAddress((void**)&b_wo_lo,  g_wo_lo);
    cudaGetSymbolAddress((void**)&b_wgu_hi, g_wgu_hi);
    cudaGetSymbolAddress((void**)&b_wgu_lo, g_wgu_lo);
    cudaGetSymbolAddress((void**)&b_wd_hi,  g_wd_hi);
    cudaGetSymbolAddress((void**)&b_wd_lo,  g_wd_lo);

    cudaFuncSetAttribute(k_attn, cudaFuncAttributeMaxDynamicSharedMemorySize, A_SMEM);
    cudaFuncSetAttribute(k_bmma<0>, cudaFuncAttributeMaxDynamicSharedMemorySize, MM_SMEM);
    cudaFuncSetAttribute(k_bmma<1>, cudaFuncAttributeMaxDynamicSharedMemorySize, MM_SMEM);
    cudaFuncSetAttribute(k_bmma<2>, cudaFuncAttributeMaxDynamicSharedMemorySize, MM_SMEM);
    cudaFuncSetAttribute(k_bmma<3>, cudaFuncAttributeMaxDynamicSharedMemorySize, MM_SMEM);

    // weight conversions
    k_wconv<<<(NH * HD * HIDD) / 2048, 256>>>(wq, b_wqkv_hi, b_wqkv_lo, NH * HD * HIDD);
    k_wconv<<<(NKV * HD * HIDD) / 2048, 256>>>(wk, b_wqkv_hi + (size_t)NH * HD * HIDD,
                                               b_wqkv_lo + (size_t)NH * HD * HIDD, NKV * HD * HIDD);
    k_wconv<<<(NKV * HD * HIDD) / 2048, 256>>>(wv, b_wqkv_hi + (size_t)(NH + NKV) * HD * HIDD,
                                               b_wqkv_lo + (size_t)(NH + NKV) * HD * HIDD, NKV * HD * HIDD);
    k_wconv<<<(HIDD * NH * HD) / 2048, 256>>>(wo, b_wo_hi, b_wo_lo, HIDD * NH * HD);
    k_wconv_ilv<<<(2 * II * HIDD) / 2048, 256>>>(wgu);
    k_wconv<<<(HIDD * II) / 2048, 256>>>(wd, b_wd_hi, b_wd_lo, HIDD * II);

    // 1-2) input RMSNorm + transpose
    k_rms_in_pass1<<<TT / 32, dim3(32, 8)>>>(hc);
    k_norm_transpose<<<dim3(TT / 32, HIDD / 32), dim3(32, 8)>>>(hc, ilw);

    // 3) fused QKV projection (q,k fp32; v bf16 hi/lo)
    k_bmma<2><<<dim3((NH + 2 * NKV) * HD / 128, TT / 128), 256, MM_SMEM>>>(
        b_h_hi, b_h_lo, b_wqkv_hi, b_wqkv_lo, nullptr, nullptr, HIDD, (NH + 2 * NKV) * HD);

    // 4) q/k RMSNorm + RoPE -> bf16 hi/lo (q scaled)
    k_qknorm_rope<<<dim3(TT, NH + NKV), HD>>>(cosb, sinb, qnw, knw);

    // 5) tensor-core causal flash attention
    k_attn<<<dim3(16, NH), 256, A_SMEM>>>();

    // 6) Wo projection + residual(x)
    k_bmma<1><<<dim3(HIDD / 128, TT / 128), 256, MM_SMEM>>>(
        b_ao_hi, b_ao_lo, b_wo_hi, b_wo_lo, p_hid, p_x, NH * HD, HIDD);

    // 7) post-LN
    k_rms_post<<<TT, 256>>>(plw);

    // 8) gate_up GEMM + fused SwiGLU -> act bf16 hi/lo
    k_bmma<3><<<dim3((2 * II) / 128, TT / 128), 256, MM_SMEM>>>(
        b_h2_hi, b_h2_lo, b_wgu_hi, b_wgu_lo, nullptr, nullptr, HIDD, 2 * II);

    // 9) down GEMM + residual
    k_bmma<1><<<dim3(HIDD / 128, TT / 128), 256, MM_SMEM>>>(
        b_act_hi, b_act_lo, b_wd_hi, b_wd_lo, p_fin, p_hid, II, HIDD);

    // 10) output transpose
    k_transpose_out<<<dim3(TT / 32, HIDD / 32), dim3(32, 8)>>>(out);
}